// round 5
// baseline (speedup 1.0000x reference)
#include <cuda_runtime.h>
#include <mma.h>
#include <math.h>

using namespace nvcuda;

namespace {
constexpr int NV = 512;
constexpr int C  = 256;
constexpr int MT = 64;       // j-rows per tile
constexpr int LDA = 260;     // padded A stride (floats); 260*4 % 16 == 0
constexpr int NWARP = 16;
constexpr int THREADS = 512;

// smem layout (floats)
constexpr int SM_A   = 0;                  // [MT][LDA]
constexpr int SM_Q   = SM_A + MT * LDA;    // [MT][C]
constexpr int SM_VE  = SM_Q + MT * C;      // [MT][C]
constexpr int SM_N   = SM_VE + MT * C;     // [C]
constexpr int SM_BK  = SM_N + C;           // [C]
constexpr int SM_SC  = SM_BK + C;          // [MT] scores / warp-reduce reuse
constexpr int SM_P   = SM_SC + MT;         // [MT] exp probs
constexpr int SM_RED = SM_P + MT;          // [512] half-combine
constexpr int SMEM_FLOATS = SM_RED + THREADS;
constexpr int SMEM_BYTES  = SMEM_FLOATS * 4;   // ~202 KB
}

// pre-rounded tf32 weights: [Wq | Wk | Wv]
__device__ float g_wt[3 * C * C];

__device__ __forceinline__ float to_tf32(float x) {
    float y; asm("cvt.rna.tf32.f32 %0, %1;" : "=f"(y) : "f"(x)); return y;
}

__global__ __launch_bounds__(256) void prep_weights(
    const float* __restrict__ Wq, const float* __restrict__ Wk, const float* __restrict__ Wv)
{
    const int idx = (blockIdx.x * 256 + threadIdx.x) * 4;
    const float* src = (blockIdx.y == 0) ? Wq : (blockIdx.y == 1 ? Wk : Wv);
    float4 t = *reinterpret_cast<const float4*>(src + idx);
    t.x = to_tf32(t.x); t.y = to_tf32(t.y); t.z = to_tf32(t.z); t.w = to_tf32(t.w);
    *reinterpret_cast<float4*>(g_wt + (size_t)blockIdx.y * C * C + idx) = t;
}

struct Acc { wmma::fragment<wmma::accumulator, 16, 16, 8, float> a[4]; };

// (64 x 256 smem A-tile) @ W^T, warp stripe = output cols [wid*16, wid*16+16).
// W pre-rounded to tf32 bit patterns -> no per-fragment conversion.
// B fragment double-buffered over k to hide global latency.
__device__ __forceinline__ void gemm16(Acc& f, const float* sA,
                                       const float* __restrict__ W, int wid) {
    wmma::fragment<wmma::matrix_a, 16, 16, 8, wmma::precision::tf32, wmma::row_major> af[4];
    wmma::fragment<wmma::matrix_b, 16, 16, 8, wmma::precision::tf32, wmma::col_major> bf[2];
#pragma unroll
    for (int m = 0; m < 4; m++) wmma::fill_fragment(f.a[m], 0.0f);

    const float* Wb = W + (size_t)(wid * 16) * C;   // col-major view, ld = C
    wmma::load_matrix_sync(bf[0], Wb, C);
#pragma unroll
    for (int k = 0; k < C; k += 8) {
        const int cur = (k >> 3) & 1;
        if (k + 8 < C) wmma::load_matrix_sync(bf[cur ^ 1], Wb + k + 8, C);
#pragma unroll
        for (int m = 0; m < 4; m++)
            wmma::load_matrix_sync(af[m], sA + m * 16 * LDA + k, LDA);
#pragma unroll
        for (int m = 0; m < 4; m++)
            wmma::mma_sync(f.a[m], af[m], bf[cur], f.a[m]);
    }
}

__device__ __forceinline__ void frag_store(Acc& f, float* dst, int ldm, int wid) {
#pragma unroll
    for (int m = 0; m < 4; m++)
        wmma::store_matrix_sync(dst + m * 16 * ldm + wid * 16, f.a[m], ldm, wmma::mem_row_major);
}

__global__ __launch_bounds__(THREADS, 1) void fused_kernel(
    const float* __restrict__ nmat, const float* __restrict__ s, const float* __restrict__ v,
    const float* __restrict__ bq, const float* __restrict__ bk, const float* __restrict__ bv,
    float* __restrict__ out)
{
    extern __shared__ float sm[];
    float* sA   = sm + SM_A;
    float* sQ   = sm + SM_Q;
    float* sVe  = sm + SM_VE;
    float* sn   = sm + SM_N;
    float* sbk  = sm + SM_BK;
    float* ssc  = sm + SM_SC;
    float* sp   = sm + SM_P;
    float* sred = sm + SM_RED;

    const int i    = blockIdx.x;
    const int tid  = threadIdx.x;
    const int wid  = tid >> 5;
    const int lane = tid & 31;
    const int ch   = tid & 255;   // channel owned for per-channel epilogues
    const int half = tid >> 8;    // j-half (0: rows 0-31, 1: rows 32-63)

    if (tid < C) { sn[tid] = nmat[(size_t)i * C + tid]; sbk[tid] = bk[tid]; }
    const float bq_r = bq[ch], bv_r = bv[ch];
    __syncthreads();

    float m_run = -1e30f, l_run = 0.0f, xacc = 0.0f;

    for (int jt = 0; jt < NV / MT; jt++) {
        const int j0 = jt * MT;
        __syncthreads();   // prev-iter smem readers done

        // build A[j][c] = tf32(n_i[c] * n_j[c] * s[i,j0+j,c])
#pragma unroll
        for (int it = 0; it < MT * (C / 4) / THREADS; it++) {
            const int idx = it * THREADS + tid;
            const int j  = idx >> 6;
            const int c4 = (idx & 63) * 4;
            const float4 n4  = *reinterpret_cast<const float4*>(nmat + (size_t)(j0 + j) * C + c4);
            const float4 s4  = *reinterpret_cast<const float4*>(s + ((size_t)i * NV + j0 + j) * C + c4);
            const float4 sn4 = *reinterpret_cast<const float4*>(sn + c4);
            float4 r;
            r.x = to_tf32(sn4.x * n4.x * s4.x);
            r.y = to_tf32(sn4.y * n4.y * s4.y);
            r.z = to_tf32(sn4.z * n4.z * s4.z);
            r.w = to_tf32(sn4.w * n4.w * s4.w);
            *reinterpret_cast<float4*>(sA + j * LDA + c4) = r;
        }
        __syncthreads();

        Acc f;
        gemm16(f, sA, g_wt, wid);               frag_store(f, sQ, C, wid);   // Q
        gemm16(f, sA, g_wt + 2 * C * C, wid);   frag_store(f, sVe, C, wid);  // V
        gemm16(f, sA, g_wt + 1 * C * C, wid);                                // K (regs)
        __syncthreads();                        // all warps done reading sA
        frag_store(f, sA, LDA, wid);            // Gk overwrites A

        // fold bq + v^2 into q-tilde: thread owns (channel ch, rows half*32..+32)
        {
            const float* vrow = v + ((size_t)i * NV + j0 + half * 32) * C + ch;
            float* q = sQ + (half * 32) * C + ch;
#pragma unroll 8
            for (int jj = 0; jj < 32; jj++) {
                const float vv = vrow[(size_t)jj * C];
                q[jj * C] = (q[jj * C] + bq_r) * vv * vv;
            }
        }
        __syncthreads();

        // scores: 16 warps x 4 rows
#pragma unroll
        for (int r = 0; r < MT / NWARP; r++) {
            const int j = wid * (MT / NWARP) + r;
            float p = 0.0f;
#pragma unroll
            for (int d = lane; d < C; d += 32)
                p += sQ[j * C + d] * (sA[j * LDA + d] + sbk[d]);
#pragma unroll
            for (int o = 16; o > 0; o >>= 1) p += __shfl_xor_sync(0xffffffffu, p, o);
            if (lane == 0) ssc[j] = p * 0.0625f;   // 1/sqrt(256)
        }
        __syncthreads();

        // online softmax (replicated scalar math on all threads)
        float tm = -1e30f;
#pragma unroll 8
        for (int j = 0; j < MT; j++) tm = fmaxf(tm, ssc[j]);
        const float m_new = fmaxf(m_run, tm);
        const float scl = __expf(m_run - m_new);
        xacc *= scl; l_run *= scl;
        if (tid < MT) sp[tid] = __expf(ssc[tid] - m_new);
        __syncthreads();
        float ls = 0.0f;
#pragma unroll 8
        for (int j = 0; j < MT; j++) ls += sp[j];
        l_run += ls;
        m_run = m_new;

        // V accumulate: x_ch += sum_j p_j (Gv[j,ch]+bv) v[j,ch] over owned rows
        {
            const float* vrow = v + ((size_t)i * NV + j0 + half * 32) * C + ch;
            const float* ve = sVe + (half * 32) * C + ch;
            const float* pp = sp + half * 32;
#pragma unroll 8
            for (int jj = 0; jj < 32; jj++)
                xacc += pp[jj] * (ve[jj * C] + bv_r) * vrow[(size_t)jj * C];
        }
    }

    // combine halves, residual, L2-normalize
    __syncthreads();
    sred[half * 256 + ch] = xacc;
    __syncthreads();
    float x = 0.0f;
    if (tid < C) x = (sred[tid] + sred[256 + tid]) / l_run + sn[tid];
    float sq = (tid < C) ? x * x : 0.0f;
#pragma unroll
    for (int o = 16; o > 0; o >>= 1) sq += __shfl_xor_sync(0xffffffffu, sq, o);
    if (lane == 0) ssc[wid] = sq;
    __syncthreads();
    float tot = 0.0f;
#pragma unroll
    for (int w = 0; w < NWARP; w++) tot += ssc[w];
    if (tid < C) out[(size_t)i * C + tid] = x * rsqrtf(tot);
}

extern "C" void kernel_launch(void* const* d_in, const int* in_sizes, int n_in,
                              void* d_out, int out_size) {
    const float* nmat = (const float*)d_in[0];
    const float* s    = (const float*)d_in[1];
    const float* v    = (const float*)d_in[2];
    const float* Wq   = (const float*)d_in[3];
    const float* bq   = (const float*)d_in[4];
    const float* Wk   = (const float*)d_in[5];
    const float* bk   = (const float*)d_in[6];
    const float* Wv   = (const float*)d_in[7];
    const float* bv   = (const float*)d_in[8];

    prep_weights<<<dim3(C * C / 1024, 3), 256>>>(Wq, Wk, Wv);

    cudaFuncSetAttribute(fused_kernel, cudaFuncAttributeMaxDynamicSharedMemorySize, SMEM_BYTES);
    fused_kernel<<<NV, THREADS, SMEM_BYTES>>>(nmat, s, v, bq, bk, bv, (float*)d_out);
}

// round 6
// speedup vs baseline: 4.0358x; 4.0358x over previous
#include <cuda_runtime.h>
#include <mma.h>
#include <math.h>

using namespace nvcuda;

namespace {
constexpr int NV = 512;   // nodes
constexpr int C  = 256;   // channels
constexpr int MT = 64;    // j-tile rows
constexpr int LDA = 264;  // padded A leading dim (floats)
constexpr int NWARP = 8;  // 256 threads

// smem layout (floats)
constexpr int SM_A   = 0;                 // [MT][LDA]
constexpr int SM_Q   = SM_A + MT * LDA;   // [MT][C]  q-tilde stage
constexpr int SM_VE  = SM_Q + MT * C;     // [MT][C]  Gv stage
constexpr int SM_N   = SM_VE + MT * C;    // [C]      n_i
constexpr int SM_BK  = SM_N + C;          // [C]      bk
constexpr int SM_SC  = SM_BK + C;         // [MT]     scores
constexpr int SM_P   = SM_SC + MT;        // [MT]     exp probs
constexpr int SM_RED = SM_P + MT;         // [NWARP]
constexpr int SMEM_FLOATS = SM_RED + NWARP;
constexpr int SMEM_BYTES  = SMEM_FLOATS * 4;   // ~201 KB
}

// pre-rounded tf32 weights: [Wq | Wk | Wv]
__device__ float g_wt[3 * C * C];

__device__ __forceinline__ float to_tf32(float x) {
    float y; asm("cvt.rna.tf32.f32 %0, %1;" : "=f"(y) : "f"(x)); return y;
}

__global__ __launch_bounds__(256) void prep_weights(
    const float* __restrict__ Wq, const float* __restrict__ Wk, const float* __restrict__ Wv)
{
    const int idx = (blockIdx.x * 256 + threadIdx.x) * 4;
    const float* src = (blockIdx.y == 0) ? Wq : (blockIdx.y == 1 ? Wk : Wv);
    float4 t = *reinterpret_cast<const float4*>(src + idx);
    t.x = to_tf32(t.x); t.y = to_tf32(t.y); t.z = to_tf32(t.z); t.w = to_tf32(t.w);
    *reinterpret_cast<float4*>(g_wt + (size_t)blockIdx.y * C * C + idx) = t;
}

struct AccFrags {
    wmma::fragment<wmma::accumulator, 16, 16, 8, float> acc[4][2];
};

// (64x256 smem A-tile, already tf32-rounded) @ W^T (pre-rounded, col-major view
// ld=C). Warp `wid` produces output cols [wid*32, wid*32+32).
// B fragments double-buffered over k: global-load latency off the mma chain.
__device__ __forceinline__ void gemm_acc(AccFrags& f, const float* sA,
                                         const float* __restrict__ W, int wid) {
    wmma::fragment<wmma::matrix_a, 16, 16, 8, wmma::precision::tf32, wmma::row_major> af[4];
    wmma::fragment<wmma::matrix_b, 16, 16, 8, wmma::precision::tf32, wmma::col_major> bf[2][2];
#pragma unroll
    for (int m = 0; m < 4; m++)
#pragma unroll
        for (int nn = 0; nn < 2; nn++) wmma::fill_fragment(f.acc[m][nn], 0.0f);

    const float* Wbase = W + (size_t)(wid * 32) * C;
    wmma::load_matrix_sync(bf[0][0], Wbase, C);
    wmma::load_matrix_sync(bf[0][1], Wbase + 16 * C, C);
#pragma unroll 2
    for (int k = 0; k < C; k += 8) {
        const int cur = (k >> 3) & 1;
        if (k + 8 < C) {
            wmma::load_matrix_sync(bf[cur ^ 1][0], Wbase + (k + 8), C);
            wmma::load_matrix_sync(bf[cur ^ 1][1], Wbase + 16 * C + (k + 8), C);
        }
#pragma unroll
        for (int m = 0; m < 4; m++)
            wmma::load_matrix_sync(af[m], sA + m * 16 * LDA + k, LDA);
#pragma unroll
        for (int m = 0; m < 4; m++)
#pragma unroll
            for (int nn = 0; nn < 2; nn++)
                wmma::mma_sync(f.acc[m][nn], af[m], bf[cur][nn], f.acc[m][nn]);
    }
}

__device__ __forceinline__ void frag_store(AccFrags& f, float* dst, int ldm, int wid) {
#pragma unroll
    for (int m = 0; m < 4; m++)
#pragma unroll
        for (int nn = 0; nn < 2; nn++)
            wmma::store_matrix_sync(dst + m * 16 * ldm + wid * 32 + nn * 16,
                                    f.acc[m][nn], ldm, wmma::mem_row_major);
}

// A[j][c] = tf32(n_i[c] * n_j[c] * s[i, j0+j, c])
__device__ __forceinline__ void build_tile(float* sA, const float* sn,
                                           const float* __restrict__ nmat,
                                           const float* __restrict__ s,
                                           int i, int j0, int tid) {
#pragma unroll 4
    for (int idx = tid; idx < MT * (C / 4); idx += 256) {
        const int j  = idx >> 6;
        const int c4 = (idx & 63) * 4;
        const float4 n4  = *reinterpret_cast<const float4*>(nmat + (size_t)(j0 + j) * C + c4);
        const float4 s4  = *reinterpret_cast<const float4*>(s + ((size_t)i * NV + j0 + j) * C + c4);
        const float4 sn4 = *reinterpret_cast<const float4*>(sn + c4);
        float4 r;
        r.x = to_tf32(sn4.x * n4.x * s4.x);
        r.y = to_tf32(sn4.y * n4.y * s4.y);
        r.z = to_tf32(sn4.z * n4.z * s4.z);
        r.w = to_tf32(sn4.w * n4.w * s4.w);
        *reinterpret_cast<float4*>(sA + j * LDA + c4) = r;
    }
}

__global__ __launch_bounds__(256, 1) void fused_kernel(
    const float* __restrict__ nmat, const float* __restrict__ s, const float* __restrict__ v,
    const float* __restrict__ bq, const float* __restrict__ bk, const float* __restrict__ bv,
    float* __restrict__ out)
{
    extern __shared__ float sm[];
    float* sA  = sm + SM_A;
    float* sQ  = sm + SM_Q;
    float* sVe = sm + SM_VE;
    float* sn  = sm + SM_N;
    float* sbk = sm + SM_BK;
    float* ssc = sm + SM_SC;
    float* sp  = sm + SM_P;
    float* red = sm + SM_RED;

    const int i = blockIdx.x;
    const int tid = threadIdx.x;
    const int wid = tid >> 5, lane = tid & 31;

    sn[tid]  = nmat[(size_t)i * C + tid];
    sbk[tid] = bk[tid];
    const float bqd = bq[tid], bvd = bv[tid];

    float m_run = -1e30f, l_run = 0.0f, xacc = 0.0f;

    for (int jt = 0; jt < NV / MT; jt++) {
        const int j0 = jt * MT;
        __syncthreads();                       // prev-iter smem readers done
        build_tile(sA, sn, nmat, s, i, j0, tid);
        __syncthreads();

        AccFrags f;
        gemm_acc(f, sA, g_wt, wid);              frag_store(f, sQ, C, wid);   // Q
        gemm_acc(f, sA, g_wt + 2 * C * C, wid);  frag_store(f, sVe, C, wid);  // V
        gemm_acc(f, sA, g_wt + 1 * C * C, wid);                               // K (regs)
        __syncthreads();                        // all warps done reading sA
        frag_store(f, sA, LDA, wid);            // Gk overwrites A

        // fold bq and v^2 into q-tilde (thread owns channel tid)
        {
            const float* vrow = v + ((size_t)i * NV + j0) * C + tid;
#pragma unroll 4
            for (int j = 0; j < MT; j++) {
                const float vv = vrow[(size_t)j * C];
                sQ[j * C + tid] = (sQ[j * C + tid] + bqd) * vv * vv;
            }
        }
        __syncthreads();                        // Gk + q~ visible

        // scores: warp handles MT/NWARP rows
#pragma unroll
        for (int r = 0; r < MT / NWARP; r++) {
            const int j = wid * (MT / NWARP) + r;
            float p = 0.0f;
#pragma unroll 4
            for (int d = lane; d < C; d += 32)
                p += sQ[j * C + d] * (sA[j * LDA + d] + sbk[d]);
#pragma unroll
            for (int o = 16; o > 0; o >>= 1) p += __shfl_xor_sync(0xffffffffu, p, o);
            if (lane == 0) ssc[j] = p * 0.0625f;   // 1/sqrt(256)
        }
        __syncthreads();

        // online softmax update (replicated scalar math on all threads)
        float tm = -1e30f;
#pragma unroll 8
        for (int j = 0; j < MT; j++) tm = fmaxf(tm, ssc[j]);
        const float m_new = fmaxf(m_run, tm);
        const float scl = __expf(m_run - m_new);
        xacc *= scl; l_run *= scl;
        if (tid < MT) sp[tid] = __expf(ssc[tid] - m_new);
        __syncthreads();
        float ls = 0.0f;
#pragma unroll 8
        for (int j = 0; j < MT; j++) ls += sp[j];
        l_run += ls;
        m_run = m_new;

        // V accumulate: x_tid += sum_j p_j (Gv[j,tid]+bv) v[j,tid]
        {
            const float* vrow = v + ((size_t)i * NV + j0) * C + tid;
#pragma unroll 4
            for (int j = 0; j < MT; j++)
                xacc += sp[j] * (sVe[j * C + tid] + bvd) * vrow[(size_t)j * C];
        }
    }

    // residual + L2 normalize
    const float x = xacc / l_run + sn[tid];
    float sq = x * x;
#pragma unroll
    for (int o = 16; o > 0; o >>= 1) sq += __shfl_xor_sync(0xffffffffu, sq, o);
    __syncthreads();
    if (lane == 0) red[wid] = sq;
    __syncthreads();
    float tot = 0.0f;
#pragma unroll
    for (int w = 0; w < NWARP; w++) tot += red[w];
    out[(size_t)i * C + tid] = x * rsqrtf(tot);
}

extern "C" void kernel_launch(void* const* d_in, const int* in_sizes, int n_in,
                              void* d_out, int out_size) {
    const float* nmat = (const float*)d_in[0];
    const float* s    = (const float*)d_in[1];
    const float* v    = (const float*)d_in[2];
    const float* Wq   = (const float*)d_in[3];
    const float* bq   = (const float*)d_in[4];
    const float* Wk   = (const float*)d_in[5];
    const float* bk   = (const float*)d_in[6];
    const float* Wv   = (const float*)d_in[7];
    const float* bv   = (const float*)d_in[8];

    prep_weights<<<dim3(C * C / 1024, 3), 256>>>(Wq, Wk, Wv);

    cudaFuncSetAttribute(fused_kernel, cudaFuncAttributeMaxDynamicSharedMemorySize, SMEM_BYTES);
    fused_kernel<<<NV, 256, SMEM_BYTES>>>(nmat, s, v, bq, bk, bv, (float*)d_out);
}